// round 1
// baseline (speedup 1.0000x reference)
#include <cuda_runtime.h>

#define B_   64
#define NI   2048
#define NO   32
#define DDO  16
#define DDI  16
#define OD   512          // NO*DDO
#define NBLK 148
#define THREADS 512

// ---- shared memory layout (floats) ----
#define SW2_PITCH 36                       // per-od row: 16 duplicated (w,w) pairs, padded to mult-of-4
#define SW2_SIZE  (OD * SW2_PITCH)         // 18432
#define SXT_OFF   SW2_SIZE                 // sXT[16][64]        1024
#define SWS_OFF   (SXT_OFF + 1024)         // sWs[16][33]         528
#define SCT_OFF   (SWS_OFF + 528)          // sCT[32][68]        2176
#define SACC_OFF  (SCT_OFF + 2176)         // sAcc[512][64]     32768
#define SMEM_FLOATS (SACC_OFF + 32768)     // 54928 floats = 219712 B

// partial sums: [NBLK][OD][B_]
__device__ float g_part[(size_t)NBLK * OD * B_];

__device__ __forceinline__ void fma2(unsigned long long& d,
                                     unsigned long long a,
                                     unsigned long long b) {
    // packed fp32x2 FMA: d = a*b + d (componentwise)
    asm("fma.rn.f32x2 %0, %1, %2, %0;" : "+l"(d) : "l"(a), "l"(b));
}

extern "C" __global__ void __launch_bounds__(THREADS, 1)
capsule_main(const float* __restrict__ X, const float* __restrict__ W)
{
    extern __shared__ float sm[];
    float* sW2  = sm;             // duplicated W tile: [od][2*i..2*i+1] = (w,w)
    float* sXT  = sm + SXT_OFF;   // x transposed: [i][b]
    float* sWs  = sm + SWS_OFF;   // Wsum: [i][o] pitch 33
    float* sCT  = sm + SCT_OFF;   // c2:   [o][b] pitch 68
    float* sAcc = sm + SACC_OFF;  // s partial: [od][b]

    const int tid  = threadIdx.x;
    const int lane = tid & 31;
    const int wid  = tid >> 5;

    // zero the accumulator (synced by the barriers inside the first n-iteration)
    for (int k = tid; k < OD * B_; k += THREADS) sAcc[k] = 0.f;

    for (int n = blockIdx.x; n < NI; n += NBLK) {
        __syncthreads();   // protect sW2/sXT reuse from previous iteration

        // ---- stage W[n] (8192 floats), duplicating each value into a (w,w) pair ----
        {
            const float4* Wg = (const float4*)(W + (size_t)n * (OD * DDI));
            #pragma unroll
            for (int k = 0; k < 4; k++) {
                int g = tid + k * THREADS;       // 0..2047 float4s
                float4 v = Wg[g];
                int od = g >> 2;
                int ib = (g & 3) * 4;
                float2* p = (float2*)(sW2 + od * SW2_PITCH + 2 * ib);
                p[0] = make_float2(v.x, v.x);
                p[1] = make_float2(v.y, v.y);
                p[2] = make_float2(v.z, v.z);
                p[3] = make_float2(v.w, v.w);
            }
        }
        // ---- stage X[:, n, :] transposed into [i][b] ----
        if (tid < 256) {
            int b  = tid >> 2;
            int ib = (tid & 3) * 4;
            float4 v = *(const float4*)(X + ((size_t)b * NI + n) * DDI + ib);
            sXT[(ib + 0) * 64 + b] = v.x;
            sXT[(ib + 1) * 64 + b] = v.y;
            sXT[(ib + 2) * 64 + b] = v.z;
            sXT[(ib + 3) * 64 + b] = v.w;
        }
        __syncthreads();

        // ---- Wsum[o][i] = sum_d W[n,o,d,i]  (thread: o=tid>>4, i=tid&15) ----
        {
            int o = tid >> 4, i = tid & 15;
            float s = 0.f;
            #pragma unroll
            for (int d = 0; d < DDO; d++) s += sW2[(o * 16 + d) * SW2_PITCH + 2 * i];
            sWs[i * 33 + o] = s;
        }
        __syncthreads();

        // ---- h + two-round routing softmax; warp wid handles b = wid + 16*bb, lane = o ----
        #pragma unroll
        for (int bb = 0; bb < 4; bb++) {
            int b = wid + 16 * bb;
            float h = 0.f;
            #pragma unroll
            for (int i = 0; i < DDI; i++)
                h = fmaf(sWs[i * 33 + lane], sXT[i * 64 + b], h);

            float b1 = h * 0.03125f;                 // c0 = 1/32 uniform
            float m = b1;
            #pragma unroll
            for (int off = 16; off; off >>= 1)
                m = fmaxf(m, __shfl_xor_sync(0xffffffffu, m, off));
            float e = __expf(b1 - m);
            float s = e;
            #pragma unroll
            for (int off = 16; off; off >>= 1)
                s += __shfl_xor_sync(0xffffffffu, s, off);
            float b2 = b1 + (e / s) * h;             // b2 = b1 + c1*h

            m = b2;
            #pragma unroll
            for (int off = 16; off; off >>= 1)
                m = fmaxf(m, __shfl_xor_sync(0xffffffffu, m, off));
            e = __expf(b2 - m);
            s = e;
            #pragma unroll
            for (int off = 16; off; off >>= 1)
                s += __shfl_xor_sync(0xffffffffu, s, off);

            sCT[lane * 68 + b] = e / s;              // c2[o][b]
        }
        __syncthreads();

        // ---- main contraction: thread tile = (b0,b0+1) x 32 od, packed f32x2 ----
        {
            const int b0  = 2 * lane;
            const int od0 = wid * 32;

            unsigned long long acc[32];
            #pragma unroll
            for (int j = 0; j < 32; j++) acc[j] = 0ull;

            #pragma unroll
            for (int i2 = 0; i2 < 8; i2++) {
                unsigned long long xA =
                    *(const unsigned long long*)(sXT + (2 * i2)     * 64 + b0);
                unsigned long long xB =
                    *(const unsigned long long*)(sXT + (2 * i2 + 1) * 64 + b0);
                #pragma unroll
                for (int j = 0; j < 32; j++) {
                    // 16B load = duplicated (w_i,w_i, w_{i+1},w_{i+1}); whole-warp broadcast
                    ulonglong2 w2 =
                        *(const ulonglong2*)(sW2 + (od0 + j) * SW2_PITCH + 4 * i2);
                    fma2(acc[j], w2.x, xA);
                    fma2(acc[j], w2.y, xB);
                }
            }

            // weight by c2 and accumulate into smem s accumulator
            unsigned long long cAp =
                *(const unsigned long long*)(sCT + (2 * wid)     * 68 + b0);
            unsigned long long cBp =
                *(const unsigned long long*)(sCT + (2 * wid + 1) * 68 + b0);
            #pragma unroll
            for (int j = 0; j < 32; j++) {
                unsigned long long c = (j < 16) ? cAp : cBp;
                unsigned long long* ap =
                    (unsigned long long*)(sAcc + (od0 + j) * 64 + b0);
                unsigned long long a = *ap;
                fma2(a, c, acc[j]);
                *ap = a;
            }
        }
    }

    __syncthreads();
    // coalesced partial writeout: g_part[blk][od*64+b]
    float* pg = g_part + (size_t)blockIdx.x * (OD * B_);
    for (int k = tid; k < OD * B_; k += THREADS) pg[k] = sAcc[k];
}

extern "C" __global__ void capsule_reduce(float* __restrict__ out)
{
    __shared__ float red[1024];
    const int t = threadIdx.x;
    const int o = blockIdx.x;            // 0..31
    const int d = t >> 6;                // 0..15
    const int b = t & 63;                // 0..63
    const int od = o * 16 + d;

    float s = 0.f;
    const float* p = g_part + (size_t)od * 64 + b;   // block reads are fully coalesced
    #pragma unroll 4
    for (int pb = 0; pb < NBLK; pb++) s += p[(size_t)pb * (OD * B_)];

    red[t] = s * s;
    __syncthreads();
    if (t < 512) red[t] += red[t + 512]; __syncthreads();
    if (t < 256) red[t] += red[t + 256]; __syncthreads();
    if (t < 128) red[t] += red[t + 128]; __syncthreads();
    if (t < 64)  red[t] += red[t + 64];  __syncthreads();

    float s2 = red[b];                                   // sum over Do of s^2
    float scale = s2 / ((1.f + s2) * sqrtf(s2 + 1e-7f)); // squash
    out[(size_t)b * (NO * DDO) + od] = scale * s;
}

extern "C" void kernel_launch(void* const* d_in, const int* in_sizes, int n_in,
                              void* d_out, int out_size)
{
    const float* a = (const float*)d_in[0];
    const float* c = (const float*)d_in[1];
    const float *X, *W;
    if (in_sizes[0] == B_ * NI * DDI) { X = a; W = c; }
    else                              { X = c; W = a; }

    size_t smem = (size_t)SMEM_FLOATS * sizeof(float);
    cudaFuncSetAttribute(capsule_main,
                         cudaFuncAttributeMaxDynamicSharedMemorySize, (int)smem);
    capsule_main<<<NBLK, THREADS, smem>>>(X, W);
    capsule_reduce<<<NO, 1024>>>((float*)d_out);
}

// round 2
// speedup vs baseline: 1.3543x; 1.3543x over previous
#include <cuda_runtime.h>

#define B_   64
#define NI   2048
#define NO   32
#define DDO  16
#define DDI  16
#define OD   512
#define NBLK 148
#define THREADS 512

typedef unsigned long long ull;

// ---- shared memory layout (floats) ----
#define WT_PITCH 516                         // [i][od] pitch (2-way STS conflict only)
#define WT_SIZE  (DDI * WT_PITCH)            // 8256
#define XD_OFF   WT_SIZE                     // sXD: float2 dup (x,x): [i][64 cols]  2048 floats
#define WS_OFF   (XD_OFF + 2048)             // sWs[16][33]                           528
#define CT_OFF   (WS_OFF + 528)              // sCT[32][68]                          2176
#define SMEM_FLOATS (CT_OFF + 2176)          // 13008 floats = 52032 B

// column swizzle for x-dup table: b -> (b%4)*16 + b/4  (makes main-loop reads conflict-free)
#define XCOL(b) ((((b) & 3) << 4) | ((b) >> 2))

// partials: [blk][o][b][d]
__device__ float g_part[(size_t)NBLK * OD * B_];

__device__ __forceinline__ void fma2(ull& d, ull a, ull b) {
    asm("fma.rn.f32x2 %0, %1, %2, %0;" : "+l"(d) : "l"(a), "l"(b));
}
__device__ __forceinline__ ull mul2(ull a, ull b) {
    ull r; asm("mul.rn.f32x2 %0, %1, %2;" : "=l"(r) : "l"(a), "l"(b)); return r;
}
__device__ __forceinline__ ull pack_dup(float a) {
    ull r; asm("mov.b64 %0, {%1, %1};" : "=l"(r) : "f"(a)); return r;
}
__device__ __forceinline__ float2 unpk(ull a) {
    float2 r; asm("mov.b64 {%0, %1}, %2;" : "=f"(r.x), "=f"(r.y) : "l"(a)); return r;
}

extern "C" __global__ void __launch_bounds__(THREADS, 1)
capsule_main(const float* __restrict__ X, const float* __restrict__ W)
{
    extern __shared__ float sm[];
    float*  sWT  = sm;                       // W transposed: [i][od], pitch 516
    float2* sXD2 = (float2*)(sm + XD_OFF);   // dup x: [i][col]  (col = XCOL(b))
    float*  sWs  = sm + WS_OFF;              // Wsum: [i][o] pitch 33
    float*  sCT  = sm + CT_OFF;              // c2:   [o][b] pitch 68

    const int tid  = threadIdx.x;
    const int lane = tid & 31;
    const int wid  = tid >> 5;
    const int o    = tid >> 4;               // main-phase tile: one o per thread
    const int bg   = tid & 15;               // 4 batches: b0..b0+3
    const int b0   = 4 * bg;

    // total accumulators: acc[odpair p][b j] = (s[o*16+2p], s[o*16+2p+1]) for b0+j
    ull acc[8][4];
    #pragma unroll
    for (int p = 0; p < 8; p++)
        #pragma unroll
        for (int j = 0; j < 4; j++) acc[p][j] = 0ull;

    // ---- prologue prefetch (n = blockIdx.x) ----
    int n = blockIdx.x;
    float4 wv[4];
    {
        const float4* Wg = (const float4*)(W + (size_t)n * (OD * DDI));
        #pragma unroll
        for (int k = 0; k < 4; k++) wv[k] = Wg[tid + k * THREADS];
    }
    float4 xv;
    if (tid < 256)
        xv = *(const float4*)(X + ((size_t)(tid >> 2) * NI + n) * DDI + (tid & 3) * 4);

    for (int it = 0; n < NI; it++, n += NBLK) {
        if (it) __syncthreads();             // prior readers done before overwrite

        // ---- stage W transposed [i][od] ----
        #pragma unroll
        for (int k = 0; k < 4; k++) {
            int g  = tid + k * THREADS;      // 0..2047
            int od = g >> 2;
            int i0 = (g & 3) * 4;
            sWT[(i0 + 0) * WT_PITCH + od] = wv[k].x;
            sWT[(i0 + 1) * WT_PITCH + od] = wv[k].y;
            sWT[(i0 + 2) * WT_PITCH + od] = wv[k].z;
            sWT[(i0 + 3) * WT_PITCH + od] = wv[k].w;
        }
        // ---- stage x duplicated (x,x) at swizzled column ----
        if (tid < 256) {
            int b  = tid >> 2;
            int i0 = (tid & 3) * 4;
            int bc = XCOL(b);
            sXD2[(i0 + 0) * 64 + bc] = make_float2(xv.x, xv.x);
            sXD2[(i0 + 1) * 64 + bc] = make_float2(xv.y, xv.y);
            sXD2[(i0 + 2) * 64 + bc] = make_float2(xv.z, xv.z);
            sXD2[(i0 + 3) * 64 + bc] = make_float2(xv.w, xv.w);
        }
        __syncthreads();

        // ---- prefetch next n (overlaps everything below) ----
        {
            int n2 = n + NBLK;
            if (n2 < NI) {
                const float4* Wg = (const float4*)(W + (size_t)n2 * (OD * DDI));
                #pragma unroll
                for (int k = 0; k < 4; k++) wv[k] = Wg[tid + k * THREADS];
                if (tid < 256)
                    xv = *(const float4*)(X + ((size_t)(tid >> 2) * NI + n2) * DDI + (tid & 3) * 4);
            }
        }

        // ---- Wsum[o][i] = sum_d W[n,o,d,i] ----
        {
            int oo = tid >> 4, ii = tid & 15;
            float s = 0.f;
            #pragma unroll
            for (int d = 0; d < DDO; d++) s += sWT[ii * WT_PITCH + oo * 16 + d];
            sWs[ii * 33 + oo] = s;
        }
        __syncthreads();

        // ---- routing: h + two softmax rounds; warp wid: b = wid+16*bb, lane = o ----
        #pragma unroll
        for (int bb = 0; bb < 4; bb++) {
            int b  = wid + 16 * bb;
            int bc = XCOL(b);
            float h = 0.f;
            #pragma unroll
            for (int i = 0; i < DDI; i++)
                h = fmaf(sWs[i * 33 + lane], sXD2[i * 64 + bc].x, h);

            float b1 = h * 0.03125f;
            float m = b1;
            #pragma unroll
            for (int off = 16; off; off >>= 1)
                m = fmaxf(m, __shfl_xor_sync(0xffffffffu, m, off));
            float e = __expf(b1 - m);
            float s = e;
            #pragma unroll
            for (int off = 16; off; off >>= 1)
                s += __shfl_xor_sync(0xffffffffu, s, off);
            float b2 = b1 + (e / s) * h;

            m = b2;
            #pragma unroll
            for (int off = 16; off; off >>= 1)
                m = fmaxf(m, __shfl_xor_sync(0xffffffffu, m, off));
            e = __expf(b2 - m);
            s = e;
            #pragma unroll
            for (int off = 16; off; off >>= 1)
                s += __shfl_xor_sync(0xffffffffu, s, off);

            sCT[lane * 68 + b] = e / s;
        }
        __syncthreads();

        // ---- main contraction: acc[p][j] += (W[2p],W[2p+1]) * c2[b]*x[b] ----
        {
            float4 cv = *(const float4*)(sCT + o * 68 + b0);
            ull c2d[4];
            c2d[0] = pack_dup(cv.x); c2d[1] = pack_dup(cv.y);
            c2d[2] = pack_dup(cv.z); c2d[3] = pack_dup(cv.w);

            #pragma unroll
            for (int i = 0; i < DDI; i++) {
                const ull* xrow = (const ull*)(sXD2 + i * 64);
                ull xs[4];
                #pragma unroll
                for (int j = 0; j < 4; j++)
                    xs[j] = mul2(xrow[j * 16 + bg], c2d[j]);   // (x,x)*(c2,c2)

                const float* wrow = sWT + i * WT_PITCH + o * 16;
                #pragma unroll
                for (int jj = 0; jj < 4; jj++) {
                    ulonglong2 w4 = *(const ulonglong2*)(wrow + 4 * jj); // 4 od
                    #pragma unroll
                    for (int j = 0; j < 4; j++) {
                        fma2(acc[2 * jj + 0][j], w4.x, xs[j]);
                        fma2(acc[2 * jj + 1][j], w4.y, xs[j]);
                    }
                }
            }
        }
    }

    // ---- writeout: g_part[blk][o][b][d], coalesced float4s ----
    float* gp = g_part + (size_t)blockIdx.x * (OD * B_) + o * 1024 + b0 * 16;
    #pragma unroll
    for (int j = 0; j < 4; j++) {
        #pragma unroll
        for (int q = 0; q < 4; q++) {
            float2 a0 = unpk(acc[2 * q + 0][j]);
            float2 a1 = unpk(acc[2 * q + 1][j]);
            *(float4*)(gp + j * 16 + 4 * q) = make_float4(a0.x, a0.y, a1.x, a1.y);
        }
    }
}

extern "C" __global__ void __launch_bounds__(256)
capsule_reduce(float* __restrict__ out)
{
    const int idx = blockIdx.x * 256 + threadIdx.x;   // 16384 threads
    const int o   = idx >> 9;
    const int r   = idx & 511;
    const int b   = r >> 3;
    const int dp  = r & 7;                            // d-pair
    const int off = o * 1024 + b * 16 + 2 * dp;

    float sx = 0.f, sy = 0.f;
    const float* p = g_part + off;
    #pragma unroll 4
    for (int pb = 0; pb < NBLK; pb++) {
        float2 v = *(const float2*)(p + (size_t)pb * (OD * B_));
        sx += v.x; sy += v.y;
    }

    float q = sx * sx + sy * sy;
    q += __shfl_xor_sync(0xffffffffu, q, 1);
    q += __shfl_xor_sync(0xffffffffu, q, 2);
    q += __shfl_xor_sync(0xffffffffu, q, 4);          // sum over 16 d (8 lanes)

    float scale = q / ((1.f + q) * sqrtf(q + 1e-7f));
    *(float2*)(out + (size_t)b * (NO * DDO) + o * 16 + 2 * dp) =
        make_float2(scale * sx, scale * sy);
}

extern "C" void kernel_launch(void* const* d_in, const int* in_sizes, int n_in,
                              void* d_out, int out_size)
{
    const float* a = (const float*)d_in[0];
    const float* c = (const float*)d_in[1];
    const float *X, *W;
    if (in_sizes[0] == B_ * NI * DDI) { X = a; W = c; }
    else                              { X = c; W = a; }

    size_t smem = (size_t)SMEM_FLOATS * sizeof(float);
    cudaFuncSetAttribute(capsule_main,
                         cudaFuncAttributeMaxDynamicSharedMemorySize, (int)smem);
    capsule_main<<<NBLK, THREADS, smem>>>(X, W);
    capsule_reduce<<<64, 256>>>((float*)d_out);
}

// round 3
// speedup vs baseline: 1.4467x; 1.0682x over previous
#include <cuda_runtime.h>

#define B_   64
#define NI   2048
#define NO   32
#define DDO  16
#define DDI  16
#define OD   512
#define NBLK 148
#define THREADS 512

typedef unsigned long long ull;

// ---- shared memory layout (floats) ----
#define WT_PITCH 516                     // [i][od] row pitch
#define WT_SIZE  (DDI * WT_PITCH)        // 8256 floats per buffer
#define XD_OFF   (2 * WT_SIZE)           // sXD: dup (x,x) float2 [i][64]  -> 2048 floats
#define WS_OFF   (XD_OFF + 2048)         // sWs[16][33]                    ->  528
#define CT_OFF   (WS_OFF + 528)          // sCT[32][68]                    -> 2176
#define SMEM_FLOATS (CT_OFF + 2176)      // 21264 floats = 85056 B

// column swizzle for x-dup table: b -> (b%4)*16 + b/4
#define XCOL(b) ((((b) & 3) << 4) | ((b) >> 2))

// partials: [blk][o][b][d]
__device__ float g_part[(size_t)NBLK * OD * B_];

__device__ __forceinline__ void fma2(ull& d, ull a, ull b) {
    asm("fma.rn.f32x2 %0, %1, %2, %0;" : "+l"(d) : "l"(a), "l"(b));
}
__device__ __forceinline__ ull mul2(ull a, ull b) {
    ull r; asm("mul.rn.f32x2 %0, %1, %2;" : "=l"(r) : "l"(a), "l"(b)); return r;
}
__device__ __forceinline__ ull pack_dup(float a) {
    ull r; asm("mov.b64 %0, {%1, %1};" : "=l"(r) : "f"(a)); return r;
}
__device__ __forceinline__ float2 unpk(ull a) {
    float2 r; asm("mov.b64 {%0, %1}, %2;" : "=f"(r.x), "=f"(r.y) : "l"(a)); return r;
}
__device__ __forceinline__ void cpa4(unsigned dst, const float* src) {
    asm volatile("cp.async.ca.shared.global [%0], [%1], 4;" :: "r"(dst), "l"(src));
}
__device__ __forceinline__ void cpa_commit() {
    asm volatile("cp.async.commit_group;");
}
__device__ __forceinline__ void cpa_wait0() {
    asm volatile("cp.async.wait_group 0;");
}

// issue the 16 transposing 4B copies for tile n into W buffer `buf`
__device__ __forceinline__ void stage_w_async(const float* __restrict__ W, int n,
                                              unsigned sbase, int tid)
{
    const float* Wg = W + (size_t)n * (OD * DDI);
    #pragma unroll
    for (int k = 0; k < 16; k++) {
        int g  = tid + k * THREADS;          // linear over [od][i], coalesced gmem
        int od = g >> 4;
        int i  = g & 15;
        cpa4(sbase + 4u * (unsigned)(i * WT_PITCH + od), Wg + g);
    }
    cpa_commit();
}

extern "C" __global__ void __launch_bounds__(THREADS, 1)
capsule_main(const float* __restrict__ X, const float* __restrict__ W)
{
    extern __shared__ float sm[];
    float2* sXD2 = (float2*)(sm + XD_OFF);
    float*  sWs  = sm + WS_OFF;
    float*  sCT  = sm + CT_OFF;

    const int tid  = threadIdx.x;
    const int lane = tid & 31;
    const int wid  = tid >> 5;
    const int o    = tid >> 4;
    const int bg   = tid & 15;
    const int b0   = 4 * bg;
    const unsigned smem_u = (unsigned)__cvta_generic_to_shared(sm);

    ull acc[8][4];
    #pragma unroll
    for (int p = 0; p < 8; p++)
        #pragma unroll
        for (int j = 0; j < 4; j++) acc[p][j] = 0ull;

    // ---- prologue: async-stage W[n0], prefetch x[n0] ----
    int n = blockIdx.x;
    stage_w_async(W, n, smem_u, tid);
    float4 xv;
    if (tid < 256)
        xv = *(const float4*)(X + ((size_t)(tid >> 2) * NI + n) * DDI + (tid & 3) * 4);

    int cur = 0;
    for (; n < NI; n += NBLK) {
        float* sWT = sm + cur * WT_SIZE;

        cpa_wait0();
        __syncthreads();                     // W[cur] ready for everyone

        // ---- stage x duplicated (x,x) at swizzled column ----
        if (tid < 256) {
            int b  = tid >> 2;
            int i0 = (tid & 3) * 4;
            int bc = XCOL(b);
            sXD2[(i0 + 0) * 64 + bc] = make_float2(xv.x, xv.x);
            sXD2[(i0 + 1) * 64 + bc] = make_float2(xv.y, xv.y);
            sXD2[(i0 + 2) * 64 + bc] = make_float2(xv.z, xv.z);
            sXD2[(i0 + 3) * 64 + bc] = make_float2(xv.w, xv.w);
        }
        // ---- Wsum[o][i] = sum_d W[n,o,d,i] (reads current W buf) ----
        {
            int oo = tid >> 4, ii = tid & 15;
            const float* r = sWT + ii * WT_PITCH + oo * 16;
            float4 a = *(const float4*)(r);
            float4 b = *(const float4*)(r + 4);
            float4 c = *(const float4*)(r + 8);
            float4 d = *(const float4*)(r + 12);
            sWs[ii * 33 + oo] = ((a.x + a.y) + (a.z + a.w)) + ((b.x + b.y) + (b.z + b.w))
                              + ((c.x + c.y) + (c.z + c.w)) + ((d.x + d.y) + (d.z + d.w));
        }
        // ---- prefetch n+NBLK: W via cp.async into other buffer, x via regs ----
        {
            int n2 = n + NBLK;
            if (n2 < NI) {
                stage_w_async(W, n2, smem_u + 4u * (unsigned)((cur ^ 1) * WT_SIZE), tid);
                if (tid < 256)
                    xv = *(const float4*)(X + ((size_t)(tid >> 2) * NI + n2) * DDI + (tid & 3) * 4);
            }
        }
        __syncthreads();                     // sXD2 + sWs visible

        // ---- routing: warp wid handles b = wid + 16*bb, lane = o ----
        #pragma unroll
        for (int bb = 0; bb < 4; bb++) {
            int b  = wid + 16 * bb;
            int bc = XCOL(b);
            float h = 0.f;
            #pragma unroll
            for (int i = 0; i < DDI; i++)
                h = fmaf(sWs[i * 33 + lane], sXD2[i * 64 + bc].x, h);

            float b1 = h * 0.03125f;
            float m = b1;
            #pragma unroll
            for (int off = 16; off; off >>= 1)
                m = fmaxf(m, __shfl_xor_sync(0xffffffffu, m, off));
            float e = __expf(b1 - m);
            float s = e;
            #pragma unroll
            for (int off = 16; off; off >>= 1)
                s += __shfl_xor_sync(0xffffffffu, s, off);
            float b2 = fmaf(__fdividef(e, s), h, b1);

            m = b2;
            #pragma unroll
            for (int off = 16; off; off >>= 1)
                m = fmaxf(m, __shfl_xor_sync(0xffffffffu, m, off));
            e = __expf(b2 - m);
            s = e;
            #pragma unroll
            for (int off = 16; off; off >>= 1)
                s += __shfl_xor_sync(0xffffffffu, s, off);

            sCT[lane * 68 + b] = __fdividef(e, s);
        }
        __syncthreads();                     // sCT visible

        // ---- main contraction: acc[p][j] += (W[2p],W[2p+1]) * (c2*x) ----
        {
            float4 cv = *(const float4*)(sCT + o * 68 + b0);
            ull c2d[4];
            c2d[0] = pack_dup(cv.x); c2d[1] = pack_dup(cv.y);
            c2d[2] = pack_dup(cv.z); c2d[3] = pack_dup(cv.w);

            #pragma unroll
            for (int i = 0; i < DDI; i++) {
                const ull* xrow = (const ull*)(sXD2 + i * 64);
                ull xs[4];
                #pragma unroll
                for (int j = 0; j < 4; j++)
                    xs[j] = mul2(xrow[j * 16 + bg], c2d[j]);

                const float* wrow = sWT + i * WT_PITCH + o * 16;
                #pragma unroll
                for (int jj = 0; jj < 4; jj++) {
                    ulonglong2 w4 = *(const ulonglong2*)(wrow + 4 * jj);
                    #pragma unroll
                    for (int j = 0; j < 4; j++) {
                        fma2(acc[2 * jj + 0][j], w4.x, xs[j]);
                        fma2(acc[2 * jj + 1][j], w4.y, xs[j]);
                    }
                }
            }
        }
        cur ^= 1;
    }

    // ---- writeout: g_part[blk][o][b][d], coalesced float4s ----
    float* gp = g_part + (size_t)blockIdx.x * (OD * B_) + o * 1024 + b0 * 16;
    #pragma unroll
    for (int j = 0; j < 4; j++) {
        #pragma unroll
        for (int q = 0; q < 4; q++) {
            float2 a0 = unpk(acc[2 * q + 0][j]);
            float2 a1 = unpk(acc[2 * q + 1][j]);
            *(float4*)(gp + j * 16 + 4 * q) = make_float4(a0.x, a0.y, a1.x, a1.y);
        }
    }
}

// grid 512 x 256: warp-per-32-elems, 8 warps split the 148 partials
extern "C" __global__ void __launch_bounds__(256)
capsule_reduce(float* __restrict__ out)
{
    __shared__ float2 red[8][32];
    const int lane = threadIdx.x & 31;
    const int w    = threadIdx.x >> 5;
    const int e    = blockIdx.x * 32 + lane;          // float2 elem in [0,16384)

    const int cnt   = 18 + (w < 4 ? 1 : 0);
    const int start = w * 18 + (w < 4 ? w : 4);

    const float2* p = ((const float2*)g_part) + e;
    float sx = 0.f, sy = 0.f;
    #pragma unroll
    for (int k = 0; k < 19; k++) {                    // predicated, fully unrolled -> MLP~19
        if (k < cnt) {
            float2 v = p[(size_t)(start + k) * 16384];
            sx += v.x; sy += v.y;
        }
    }
    red[w][lane] = make_float2(sx, sy);
    __syncthreads();

    if (w == 0) {
        sx = 0.f; sy = 0.f;
        #pragma unroll
        for (int k = 0; k < 8; k++) { float2 v = red[k][lane]; sx += v.x; sy += v.y; }

        float q = sx * sx + sy * sy;
        q += __shfl_xor_sync(0xffffffffu, q, 1);
        q += __shfl_xor_sync(0xffffffffu, q, 2);
        q += __shfl_xor_sync(0xffffffffu, q, 4);      // sum over 16 d (8 lanes)

        float scale = q / ((1.f + q) * sqrtf(q + 1e-7f));
        int o = e >> 9, b = (e >> 3) & 63, dp = e & 7;
        *(float2*)(out + (size_t)b * (NO * DDO) + o * 16 + 2 * dp) =
            make_float2(scale * sx, scale * sy);
    }
}

extern "C" void kernel_launch(void* const* d_in, const int* in_sizes, int n_in,
                              void* d_out, int out_size)
{
    const float* a = (const float*)d_in[0];
    const float* c = (const float*)d_in[1];
    const float *X, *W;
    if (in_sizes[0] == B_ * NI * DDI) { X = a; W = c; }
    else                              { X = c; W = a; }

    size_t smem = (size_t)SMEM_FLOATS * sizeof(float);
    cudaFuncSetAttribute(capsule_main,
                         cudaFuncAttributeMaxDynamicSharedMemorySize, (int)smem);
    capsule_main<<<NBLK, THREADS, smem>>>(X, W);
    capsule_reduce<<<512, 256>>>((float*)d_out);
}